// round 15
// baseline (speedup 1.0000x reference)
#include <cuda_runtime.h>
#include <cfloat>
#include <climits>
#include <math.h>

// Beam search step: P=32 prompts, D=8 beams, V=128000, S=2048.
// Ordering by alive_lp + log(p) == ordering by m = p * exp(alive_lp) (monotone).
// k1: pass 1 = per-THREAD chunk maxima (16 independent coalesced float4 loads,
//     register FMAX chain, no shuffles) -> 256 disjoint chunks per block;
//     tau_b = 16th largest of the 256 maxima (<= block 16th <= global 16th,
//     exact-safe). pass 2: only threads whose own max >= tau re-read their
//     16 float4s (L2-hit) and append survivors. still_prompt skipped.
// k2: dual concurrent register tournaments (named barriers) + selection.
// k3: 512-block gather/convert of output sequence rows.

#define P_ 32
#define D_ 8
#define V_ 128000
#define S_ 2048
#define NBLK 64          // blocks per prompt in k1 (8 per beam)
#define CHUNK 16000      // elements per k1 block (V/8) = 4000 float4
#define N4 4000          // float4s per block
#define ITER 16          // float4s per thread (ceil(4000/256))
#define EOS_ID 2
#define MASK_INF 10000000.0f
#define CAP  32768       // candidate capacity per prompt (scaled list)
#define CAP0 8192        // candidate capacity per prompt (beam-0 raw list)
#define TILEH 2048       // candidates per half-tournament tile (16 slots * 128 thr)

// output layout (flat float32, tuple concat order)
#define OFF_ATTN 0
#define OFF_ASEQ 256
#define OFF_ALP  524544
#define OFF_FSEQ 524800
#define OFF_FLP  1049088

__device__ int   g_cnt[P_];              // zero-init at load; k2 resets
__device__ int   g_cnt0[P_];
__device__ float g_cv[P_ * CAP];
__device__ int   g_ci[P_ * CAP];
__device__ float g_c0v[P_ * CAP0];
__device__ int   g_c0i[P_ * CAP0];
__device__ int4  g_desc[2 * P_ * D_];    // {buf(0=alive,1=fin), src_beam, token, subpos(-1 none)}

#define FULLM 0xffffffffu
#define HBAR(id) asm volatile("bar.sync %0, %1;" :: "r"(id), "r"(128) : "memory")

__device__ __forceinline__ float max4(float4 v) {
    return fmaxf(fmaxf(v.x, v.y), fmaxf(v.z, v.w));
}

// ---------------- Kernel 1: thread-chunk self-threshold + sparse re-read ----
__global__ void __launch_bounds__(256)
k1_scan(const float* __restrict__ probs, const float* __restrict__ alive_lp,
        const int* __restrict__ still_prompt, const int* __restrict__ is_first) {
    int blk = blockIdx.x;
    int p = blk >> 6;
    if (still_prompt[p]) return;              // passthrough prompt: no work
    int b = blk & 63;
    int d = b >> 3;
    int part = b & 7;
    int t = threadIdx.x, w = t >> 5, lane = t & 31;

    __shared__ float s_tm[256];
    __shared__ float s_tau;

    const float4* base = (const float4*)(probs + (long)(p * D_ + d) * V_ + part * CHUNK);

    // ---- pass 1: per-thread max over 16 strided (coalesced) float4 loads ----
    float tm = -FLT_MAX;
#pragma unroll
    for (int i = 0; i < ITER; i++) {
        int j = i * 256 + t;
        if (j < N4) tm = fmaxf(tm, max4(base[j]));
    }
    s_tm[t] = tm;
    __syncthreads();

    // ---- tau_b = 16th largest of 256 thread maxima (warp 0) ----------------
    if (w == 0) {
        float vv[8];
#pragma unroll
        for (int j = 0; j < 8; j++) vv[j] = s_tm[lane + 32 * j];
        float last = -FLT_MAX;
#pragma unroll
        for (int k = 0; k < 16; k++) {
            float bv = vv[0]; int bs = 0;
#pragma unroll
            for (int j = 1; j < 8; j++)
                if (vv[j] > bv) { bv = vv[j]; bs = j; }
            float cb = bv; int cl = lane;
#pragma unroll
            for (int off = 16; off; off >>= 1) {
                float ov = __shfl_xor_sync(FULLM, cb, off);
                int   ol = __shfl_xor_sync(FULLM, cl, off);
                if (ov > cb || (ov == cb && ol < cl)) { cb = ov; cl = ol; }
            }
            last = cb;
            if (lane == cl) vv[bs] = -FLT_MAX;
        }
        if (lane == 0) s_tau = last;
    }
    __syncthreads();

    float tauR = s_tau;                       // raw-space threshold (shared by both lists)

    // ---- pass 2: only threads whose own max >= tau re-read (L2-hit) --------
    if (tm >= tauR) {
        float scale = expf(alive_lp[p * D_ + d]);
        bool do0 = (d == 0) && (is_first[p] != 0);
        int fb0 = d * V_ + part * CHUNK;
#pragma unroll
        for (int i = 0; i < ITER; i++) {
            int j = i * 256 + t;
            if (j >= N4) continue;
            float4 v = base[j];
            int fb = fb0 + j * 4;
            float vx[4] = {v.x, v.y, v.z, v.w};
#pragma unroll
            for (int cc = 0; cc < 4; cc++) {
                if (vx[cc] >= tauR) {
                    int pos = atomicAdd(&g_cnt[p], 1);
                    if (pos < CAP) { g_cv[p * CAP + pos] = vx[cc] * scale; g_ci[p * CAP + pos] = fb + cc; }
                    if (do0) {                // d==0: flat idx == token id
                        int pos0 = atomicAdd(&g_cnt0[p], 1);
                        if (pos0 < CAP0) { g_c0v[p * CAP0 + pos0] = vx[cc]; g_c0i[p * CAP0 + pos0] = fb + cc; }
                    }
                }
            }
        }
    }
}

// -------- half-block tournament: sorted top-16, 128 threads, named barrier ---
struct HalfScratch {
    float swv[4]; int swi[4]; int swt[4];
    int   s_win;
};

__device__ void half_top16(const float* __restrict__ gv, const int* __restrict__ gi,
                           int cnt, volatile float* bestv, volatile int* besti,
                           volatile HalfScratch* sc, int tb, int barid) {
    int t = threadIdx.x;
    int lt = t - tb;                          // 0..127
    int w2 = lt >> 5;                         // 0..3
    int lane = t & 31;
    float rv[17]; int ri[17];
    int ntile = (cnt + TILEH - 1) / TILEH;
    if (ntile < 1) ntile = 1;

    for (int tile = 0; tile < ntile; tile++) {
        int base = tile * TILEH;
#pragma unroll
        for (int k = 0; k < 16; k++) {
            int j = base + k * 128 + lt;
            bool ok = (j < cnt);
            rv[k] = ok ? gv[j] : -FLT_MAX;
            ri[k] = ok ? gi[j] : INT_MAX;
        }
        if (tile > 0 && lt < 16) { rv[16] = bestv[lt]; ri[16] = besti[lt]; }
        else                     { rv[16] = -FLT_MAX; ri[16] = INT_MAX; }

        for (int r = 0; r < 16; r++) {
            float bv = rv[0]; int bi = ri[0]; int bs = 0;
#pragma unroll
            for (int k = 1; k < 17; k++)
                if (rv[k] > bv || (rv[k] == bv && ri[k] < bi)) { bv = rv[k]; bi = ri[k]; bs = k; }
            int bt = lt;
#pragma unroll
            for (int off = 16; off; off >>= 1) {
                float ov = __shfl_xor_sync(FULLM, bv, off);
                int   oi = __shfl_xor_sync(FULLM, bi, off);
                int   ot = __shfl_xor_sync(FULLM, bt, off);
                if (ov > bv || (ov == bv && oi < bi)) { bv = ov; bi = oi; bt = ot; }
            }
            if (lane == 0) { sc->swv[w2] = bv; sc->swi[w2] = bi; sc->swt[w2] = bt; }
            HBAR(barid);
            if (lt == 0) {
                float fv = sc->swv[0]; int fi = sc->swi[0]; int ft = sc->swt[0];
#pragma unroll
                for (int q = 1; q < 4; q++)
                    if (sc->swv[q] > fv || (sc->swv[q] == fv && sc->swi[q] < fi)) {
                        fv = sc->swv[q]; fi = sc->swi[q]; ft = sc->swt[q];
                    }
                bestv[r] = fv; besti[r] = fi; sc->s_win = ft;
            }
            HBAR(barid);
            if (lt == sc->s_win) { rv[bs] = -FLT_MAX; ri[bs] = INT_MAX; }
        }
        HBAR(barid);
    }
}

// ---------------- Kernel 2: dual tournament + beam-search selection ----------
__global__ void __launch_bounds__(256)
k2_select(const float* __restrict__ alive_lp, const float* __restrict__ fin_lp,
          const int* __restrict__ still_prompt,
          const int* __restrict__ is_first,
          const int* __restrict__ cur_pos_p, float* __restrict__ out) {
    int p = blockIdx.x;
    int t = threadIdx.x;

    __shared__ float fv[16];  __shared__ int fi[16];
    __shared__ float fv0[16]; __shared__ int fi0[16];
    __shared__ HalfScratch scA, scB;

    bool sp = still_prompt[p] != 0;
    bool first = is_first[p] != 0;
    int cnt  = min(g_cnt[p], CAP);
    int cnt0 = min(g_cnt0[p], CAP0);

    if (!sp) {
        if (t < 128)
            half_top16(g_cv + p * CAP, g_ci + p * CAP, cnt, fv, fi,
                       (volatile HalfScratch*)&scA, 0, 1);
        else if (first)
            half_top16(g_c0v + p * CAP0, g_c0i + p * CAP0, cnt0, fv0, fi0,
                       (volatile HalfScratch*)&scB, 128, 2);
    }
    __syncthreads();

    if (t == 0) {
        g_cnt[p] = 0; g_cnt0[p] = 0;          // reset for next graph replay
        int cp = *cur_pos_p;

        float lp16[16]; int tok16[16], beam16[16]; bool fin16[16];
        if (!sp) {
            for (int k = 0; k < 16; k++) {
                int idx = fi[k];
                int bm = idx / V_;
                beam16[k] = bm;
                tok16[k]  = idx - bm * V_;
                lp16[k]   = logf(fv[k]);      // log(p*e^a) == a + log p
            }
            if (first) {
                float al0 = alive_lp[p * D_];
                for (int k = 0; k < 16; k++) {
                    tok16[k] = fi0[k];        // flat idx within beam 0 == token
                    lp16[k]  = al0 + logf(fv0[k]);
                }
            }
            for (int k = 0; k < 16; k++) fin16[k] = (tok16[k] == EOS_ID);
        }

        int na[8]; float nav[8];
        int nf[8]; float nfv[8];
        if (!sp) {
            float am[16]; bool used[16];
            for (int k = 0; k < 16; k++) { am[k] = lp16[k] + (fin16[k] ? -MASK_INF : 0.0f); used[k] = false; }
            for (int j = 0; j < 8; j++) {
                int bi = -1; float bv = 0.0f;
                for (int k = 0; k < 16; k++)
                    if (!used[k] && (bi < 0 || am[k] > bv)) { bi = k; bv = am[k]; }
                used[bi] = true; na[j] = bi; nav[j] = bv;
            }
            float cl[24]; bool used2[24];
            for (int j = 0; j < 8; j++) cl[j] = fin_lp[p * D_ + j];
            for (int k = 0; k < 16; k++) cl[8 + k] = lp16[k] + (fin16[k] ? 0.0f : -MASK_INF);
            for (int k = 0; k < 24; k++) used2[k] = false;
            for (int j = 0; j < 8; j++) {
                int bi = -1; float bv = 0.0f;
                for (int k = 0; k < 24; k++)
                    if (!used2[k] && (bi < 0 || cl[k] > bv)) { bi = k; bv = cl[k]; }
                used2[bi] = true; nf[j] = bi; nfv[j] = bv;
            }
        }

        for (int j = 0; j < 8; j++) {
            out[OFF_ATTN + p * D_ + j] = sp ? (float)j : (float)beam16[na[j]];
            out[OFF_ALP  + p * D_ + j] = sp ? alive_lp[p * D_ + j] : nav[j];
            out[OFF_FLP  + p * D_ + j] = sp ? fin_lp[p * D_ + j]   : nfv[j];

            int4 da, df;
            if (sp) {
                da = make_int4(0, j, 0, -1);
                df = make_int4(1, j, 0, -1);
            } else {
                da = make_int4(0, beam16[na[j]], tok16[na[j]], cp);
                if (nf[j] < 8) df = make_int4(1, nf[j], 0, -1);
                else { int k = nf[j] - 8; df = make_int4(0, beam16[k], tok16[k], cp); }
            }
            g_desc[p * D_ + j] = da;
            g_desc[P_ * D_ + p * D_ + j] = df;
        }
    }
}

// ---------------- Kernel 3: gather output sequences --------------------------
__global__ void __launch_bounds__(256)
k3_gather(const int* __restrict__ alive_seq, const int* __restrict__ fin_seq,
          float* __restrict__ out) {
    int r = blockIdx.x;                       // 0..511
    int4 dsc = g_desc[r];
    bool isAlive = r < P_ * D_;
    int rr = isAlive ? r : r - P_ * D_;
    int p = rr >> 3;
    const int* srcbase = (dsc.x ? fin_seq : alive_seq) + (long)(p * D_ + dsc.y) * S_;
    long dst = (isAlive ? (long)OFF_ASEQ : (long)OFF_FSEQ) + (long)rr * S_;
    const int4* s4 = (const int4*)srcbase;
    float4* o4 = (float4*)(out + dst);
    int subpos = dsc.w, tok = dsc.z;
    for (int j = threadIdx.x; j < S_ / 4; j += 256) {
        int4 v = s4[j];
        int base = j * 4;
        if (subpos >= base && subpos < base + 4) {
            int* vp = (int*)&v;
            vp[subpos - base] = tok;
        }
        o4[j] = make_float4((float)v.x, (float)v.y, (float)v.z, (float)v.w);
    }
}

extern "C" void kernel_launch(void* const* d_in, const int* in_sizes, int n_in,
                              void* d_out, int out_size) {
    const float* probs        = (const float*)d_in[0];
    const int*   alive_seq    = (const int*)d_in[1];
    const int*   fin_seq      = (const int*)d_in[2];
    const float* alive_lp     = (const float*)d_in[3];
    const float* fin_lp       = (const float*)d_in[4];
    const int*   still_prompt = (const int*)d_in[5];
    const int*   is_first     = (const int*)d_in[6];
    const int*   cur_pos      = (const int*)d_in[7];
    float* out = (float*)d_out;

    k1_scan<<<P_ * NBLK, 256>>>(probs, alive_lp, still_prompt, is_first);
    k2_select<<<P_, 256>>>(alive_lp, fin_lp, still_prompt, is_first, cur_pos, out);
    k3_gather<<<2 * P_ * D_, 256>>>(alive_seq, fin_seq, out);
}

// round 16
// speedup vs baseline: 1.1249x; 1.1249x over previous
#include <cuda_runtime.h>
#include <cfloat>
#include <climits>
#include <math.h>

// Beam search step: P=32 prompts, D=8 beams, V=128000, S=2048.
// Ordering by alive_lp + log(p) == ordering by m = p * exp(alive_lp) (monotone).
// k1 (R14-proven, 31.9us): pass 1 = 125 chunk maxima (1 warp-load chunk = 128
//     elems); tau_b = 16th largest (<= block 16th <= global 16th, exact-safe);
//     pass 2 re-reads only chunks with max >= tau (L2-hit) and appends.
// k23 (fused): 512 blocks; each of the 16 blocks per prompt REDUNDANTLY runs
//     the dual register tournament + selection (parallel across SMs), then
//     gathers its own output row. Counter reset via readers-counter: every
//     block reads cnt BEFORE incrementing; the 16th arriver resets.

#define P_ 32
#define D_ 8
#define V_ 128000
#define S_ 2048
#define NBLK 64          // blocks per prompt in k1 (8 per beam)
#define CHUNK 16000      // elements per k1 block (V/8) = 4000 float4
#define NC 125           // chunks per block (32 float4 = 128 elems each)
#define EOS_ID 2
#define MASK_INF 10000000.0f
#define CAP  32768       // candidate capacity per prompt (scaled list)
#define CAP0 8192        // candidate capacity per prompt (beam-0 raw list)
#define TILEH 2048       // candidates per half-tournament tile (16 slots * 128 thr)

// output layout (flat float32, tuple concat order)
#define OFF_ATTN 0
#define OFF_ASEQ 256
#define OFF_ALP  524544
#define OFF_FSEQ 524800
#define OFF_FLP  1049088

__device__ int   g_cnt[P_];              // zero-init at load; k23 resets (last reader)
__device__ int   g_cnt0[P_];
__device__ int   g_readers[P_];          // monotone; arrival counter for reset
__device__ float g_cv[P_ * CAP];
__device__ int   g_ci[P_ * CAP];
__device__ float g_c0v[P_ * CAP0];
__device__ int   g_c0i[P_ * CAP0];

#define FULLM 0xffffffffu
#define HBAR(id) asm volatile("bar.sync %0, %1;" :: "r"(id), "r"(128) : "memory")

__device__ __forceinline__ float max4(float4 v) {
    return fmaxf(fmaxf(v.x, v.y), fmaxf(v.z, v.w));
}

// ---------------- Kernel 1: fine-chunk self-threshold + sparse re-read ------
__global__ void __launch_bounds__(256)
k1_scan(const float* __restrict__ probs, const float* __restrict__ alive_lp,
        const int* __restrict__ still_prompt, const int* __restrict__ is_first) {
    int blk = blockIdx.x;
    int p = blk >> 6;
    if (still_prompt[p]) return;              // passthrough prompt: no work
    int b = blk & 63;
    int d = b >> 3;
    int part = b & 7;
    int t = threadIdx.x, w = t >> 5, lane = t & 31;

    __shared__ float scm[NC];
    __shared__ float s_tau;

    const float4* base = (const float4*)(probs + (long)(p * D_ + d) * V_ + part * CHUNK);

    // ---- pass 1: 125 chunk maxima, one coalesced warp-load per chunk --------
    for (int c = w; c < NC; c += 8) {
        float m = max4(base[c * 32 + lane]);
#pragma unroll
        for (int off = 16; off; off >>= 1)
            m = fmaxf(m, __shfl_xor_sync(FULLM, m, off));
        if (lane == 0) scm[c] = m;
    }
    __syncthreads();

    // ---- tau_b = 16th largest of the 125 maxima (warp 0) -------------------
    if (w == 0) {
        float vv[4];
        vv[0] = scm[lane];
        vv[1] = (lane + 32 < NC) ? scm[lane + 32] : -FLT_MAX;
        vv[2] = (lane + 64 < NC) ? scm[lane + 64] : -FLT_MAX;
        vv[3] = (lane + 96 < NC) ? scm[lane + 96] : -FLT_MAX;
        float last = -FLT_MAX;
#pragma unroll
        for (int k = 0; k < 16; k++) {
            float bv = vv[0]; int bs = 0;
#pragma unroll
            for (int j = 1; j < 4; j++)
                if (vv[j] > bv) { bv = vv[j]; bs = j; }
            float cb = bv; int cl = lane;
#pragma unroll
            for (int off = 16; off; off >>= 1) {
                float ov = __shfl_xor_sync(FULLM, cb, off);
                int   ol = __shfl_xor_sync(FULLM, cl, off);
                if (ov > cb || (ov == cb && ol < cl)) { cb = ov; cl = ol; }
            }
            last = cb;
            if (lane == cl) vv[bs] = -FLT_MAX;
        }
        if (lane == 0) s_tau = last;
    }
    __syncthreads();

    float tauR = s_tau;                       // raw-space threshold (shared by both lists)
    float scale = expf(alive_lp[p * D_ + d]);
    bool do0 = (d == 0) && (is_first[p] != 0);
    int fb0 = d * V_ + part * CHUNK;

    // ---- pass 2: re-read ONLY chunks with max >= tau (warp-uniform skip) ----
    for (int c = w; c < NC; c += 8) {
        if (scm[c] < tauR) continue;          // ~86% skipped
        float4 v = base[c * 32 + lane];       // L2-hit
        int fb = fb0 + (c * 32 + lane) * 4;
        float vx[4] = {v.x, v.y, v.z, v.w};
#pragma unroll
        for (int cc = 0; cc < 4; cc++) {
            if (vx[cc] >= tauR) {
                int pos = atomicAdd(&g_cnt[p], 1);
                if (pos < CAP) { g_cv[p * CAP + pos] = vx[cc] * scale; g_ci[p * CAP + pos] = fb + cc; }
                if (do0) {                    // d==0: flat idx == token id
                    int pos0 = atomicAdd(&g_cnt0[p], 1);
                    if (pos0 < CAP0) { g_c0v[p * CAP0 + pos0] = vx[cc]; g_c0i[p * CAP0 + pos0] = fb + cc; }
                }
            }
        }
    }
}

// -------- half-block tournament: sorted top-16, 128 threads, named barrier ---
struct HalfScratch {
    float swv[4]; int swi[4]; int swt[4];
    int   s_win;
};

__device__ void half_top16(const float* __restrict__ gv, const int* __restrict__ gi,
                           int cnt, volatile float* bestv, volatile int* besti,
                           volatile HalfScratch* sc, int tb, int barid) {
    int t = threadIdx.x;
    int lt = t - tb;                          // 0..127
    int w2 = lt >> 5;                         // 0..3
    int lane = t & 31;
    float rv[17]; int ri[17];
    int ntile = (cnt + TILEH - 1) / TILEH;
    if (ntile < 1) ntile = 1;

    for (int tile = 0; tile < ntile; tile++) {
        int base = tile * TILEH;
#pragma unroll
        for (int k = 0; k < 16; k++) {
            int j = base + k * 128 + lt;
            bool ok = (j < cnt);
            rv[k] = ok ? gv[j] : -FLT_MAX;
            ri[k] = ok ? gi[j] : INT_MAX;
        }
        if (tile > 0 && lt < 16) { rv[16] = bestv[lt]; ri[16] = besti[lt]; }
        else                     { rv[16] = -FLT_MAX; ri[16] = INT_MAX; }

        for (int r = 0; r < 16; r++) {
            float bv = rv[0]; int bi = ri[0]; int bs = 0;
#pragma unroll
            for (int k = 1; k < 17; k++)
                if (rv[k] > bv || (rv[k] == bv && ri[k] < bi)) { bv = rv[k]; bi = ri[k]; bs = k; }
            int bt = lt;
#pragma unroll
            for (int off = 16; off; off >>= 1) {
                float ov = __shfl_xor_sync(FULLM, bv, off);
                int   oi = __shfl_xor_sync(FULLM, bi, off);
                int   ot = __shfl_xor_sync(FULLM, bt, off);
                if (ov > bv || (ov == bv && oi < bi)) { bv = ov; bi = oi; bt = ot; }
            }
            if (lane == 0) { sc->swv[w2] = bv; sc->swi[w2] = bi; sc->swt[w2] = bt; }
            HBAR(barid);
            if (lt == 0) {
                float fv = sc->swv[0]; int fi = sc->swi[0]; int ft = sc->swt[0];
#pragma unroll
                for (int q = 1; q < 4; q++)
                    if (sc->swv[q] > fv || (sc->swv[q] == fv && sc->swi[q] < fi)) {
                        fv = sc->swv[q]; fi = sc->swi[q]; ft = sc->swt[q];
                    }
                bestv[r] = fv; besti[r] = fi; sc->s_win = ft;
            }
            HBAR(barid);
            if (lt == sc->s_win) { rv[bs] = -FLT_MAX; ri[bs] = INT_MAX; }
        }
        HBAR(barid);
    }
}

// ------- Kernel 2+3 fused: redundant selection + per-row gather --------------
// grid = 512: block r -> prompt p = r>>4, row sub = r&15 (0-7 alive, 8-15 fin).
__global__ void __launch_bounds__(256)
k23(const float* __restrict__ alive_lp, const float* __restrict__ fin_lp,
    const int* __restrict__ still_prompt, const int* __restrict__ is_first,
    const int* __restrict__ cur_pos_p,
    const int* __restrict__ alive_seq, const int* __restrict__ fin_seq,
    float* __restrict__ out) {
    int r = blockIdx.x;
    int p = r >> 4;
    int sub = r & 15;
    int t = threadIdx.x;

    __shared__ float fv[16];  __shared__ int fi[16];
    __shared__ float fv0[16]; __shared__ int fi0[16];
    __shared__ HalfScratch scA, scB;
    __shared__ int s_cnt[2];
    __shared__ int4 s_desc;

    bool sp = still_prompt[p] != 0;
    bool first = is_first[p] != 0;

    // read counters BEFORE arrival-increment; last arriver resets them.
    if (t == 0) {
        int c  = *(volatile int*)&g_cnt[p];
        int c0 = *(volatile int*)&g_cnt0[p];
        s_cnt[0] = min(c, CAP);
        s_cnt[1] = min(c0, CAP0);
        __threadfence();
        int old = atomicAdd(&g_readers[p], 1);
        if ((old & 15) == 15) { g_cnt[p] = 0; g_cnt0[p] = 0; }
    }
    __syncthreads();
    int cnt = s_cnt[0], cnt0 = s_cnt[1];

    if (!sp) {
        if (t < 128)
            half_top16(g_cv + p * CAP, g_ci + p * CAP, cnt, fv, fi,
                       (volatile HalfScratch*)&scA, 0, 1);
        else if (first)
            half_top16(g_c0v + p * CAP0, g_c0i + p * CAP0, cnt0, fv0, fi0,
                       (volatile HalfScratch*)&scB, 128, 2);
    }
    __syncthreads();

    if (t == 0) {
        int cp = *cur_pos_p;

        float lp16[16]; int tok16[16], beam16[16]; bool fin16[16];
        int na[8]; float nav[8];
        int nf[8]; float nfv[8];
        if (!sp) {
            for (int k = 0; k < 16; k++) {
                int idx = fi[k];
                int bm = idx / V_;
                beam16[k] = bm;
                tok16[k]  = idx - bm * V_;
                lp16[k]   = logf(fv[k]);      // log(p*e^a) == a + log p
            }
            if (first) {
                float al0 = alive_lp[p * D_];
                for (int k = 0; k < 16; k++) {
                    tok16[k] = fi0[k];        // flat idx within beam 0 == token
                    lp16[k]  = al0 + logf(fv0[k]);
                }
            }
            for (int k = 0; k < 16; k++) fin16[k] = (tok16[k] == EOS_ID);

            float am[16]; bool used[16];
            for (int k = 0; k < 16; k++) { am[k] = lp16[k] + (fin16[k] ? -MASK_INF : 0.0f); used[k] = false; }
            for (int j = 0; j < 8; j++) {
                int bi = -1; float bv = 0.0f;
                for (int k = 0; k < 16; k++)
                    if (!used[k] && (bi < 0 || am[k] > bv)) { bi = k; bv = am[k]; }
                used[bi] = true; na[j] = bi; nav[j] = bv;
            }
            float cl[24]; bool used2[24];
            for (int j = 0; j < 8; j++) cl[j] = fin_lp[p * D_ + j];
            for (int k = 0; k < 16; k++) cl[8 + k] = lp16[k] + (fin16[k] ? 0.0f : -MASK_INF);
            for (int k = 0; k < 24; k++) used2[k] = false;
            for (int j = 0; j < 8; j++) {
                int bi = -1; float bv = 0.0f;
                for (int k = 0; k < 24; k++)
                    if (!used2[k] && (bi < 0 || cl[k] > bv)) { bi = k; bv = cl[k]; }
                used2[bi] = true; nf[j] = bi; nfv[j] = bv;
            }
        }

        // scalar outputs only from the sub==0 block
        if (sub == 0) {
            for (int j = 0; j < 8; j++) {
                out[OFF_ATTN + p * D_ + j] = sp ? (float)j : (float)beam16[na[j]];
                out[OFF_ALP  + p * D_ + j] = sp ? alive_lp[p * D_ + j] : nav[j];
                out[OFF_FLP  + p * D_ + j] = sp ? fin_lp[p * D_ + j]   : nfv[j];
            }
        }

        // this block's own row descriptor
        int4 dsc;
        if (sub < 8) {                        // alive row j = sub
            int j = sub;
            if (sp) dsc = make_int4(0, j, 0, -1);
            else    dsc = make_int4(0, beam16[na[j]], tok16[na[j]], cp);
        } else {                              // finished row j = sub-8
            int j = sub - 8;
            if (sp) dsc = make_int4(1, j, 0, -1);
            else if (nf[j] < 8) dsc = make_int4(1, nf[j], 0, -1);
            else { int k = nf[j] - 8; dsc = make_int4(0, beam16[k], tok16[k], cp); }
        }
        s_desc = dsc;
    }
    __syncthreads();

    // ---- gather this block's row (2048 tokens) ----
    int4 dsc = s_desc;
    int row = (sub < 8) ? sub : sub - 8;
    const int* srcbase = (dsc.x ? fin_seq : alive_seq) + (long)(p * D_ + dsc.y) * S_;
    long dst = (sub < 8 ? (long)OFF_ASEQ : (long)OFF_FSEQ) + (long)(p * D_ + row) * S_;
    const int4* s4 = (const int4*)srcbase;
    float4* o4 = (float4*)(out + dst);
    int subpos = dsc.w, tok = dsc.z;
    for (int j = t; j < S_ / 4; j += 256) {
        int4 v = s4[j];
        int base = j * 4;
        if (subpos >= base && subpos < base + 4) {
            int* vp = (int*)&v;
            vp[subpos - base] = tok;
        }
        o4[j] = make_float4((float)v.x, (float)v.y, (float)v.z, (float)v.w);
    }
}

extern "C" void kernel_launch(void* const* d_in, const int* in_sizes, int n_in,
                              void* d_out, int out_size) {
    const float* probs        = (const float*)d_in[0];
    const int*   alive_seq    = (const int*)d_in[1];
    const int*   fin_seq      = (const int*)d_in[2];
    const float* alive_lp     = (const float*)d_in[3];
    const float* fin_lp       = (const float*)d_in[4];
    const int*   still_prompt = (const int*)d_in[5];
    const int*   is_first     = (const int*)d_in[6];
    const int*   cur_pos      = (const int*)d_in[7];
    float* out = (float*)d_out;

    k1_scan<<<P_ * NBLK, 256>>>(probs, alive_lp, still_prompt, is_first);
    k23<<<2 * P_ * D_, 256>>>(alive_lp, fin_lp, still_prompt, is_first, cur_pos,
                              alive_seq, fin_seq, out);
}

// round 17
// speedup vs baseline: 1.3443x; 1.1950x over previous
#include <cuda_runtime.h>
#include <cfloat>
#include <climits>
#include <math.h>

// Beam search step: P=32 prompts, D=8 beams, V=128000, S=2048.
// Ordering by alive_lp + log(p) == ordering by m = p * exp(alive_lp) (monotone).
// k1: pass 1 = per-THREAD chunk maxima via a ROLLED x4 loop of 4 batched
//     coalesced float4 loads (MLP=4, ~40 regs, no shuffles in hot loop);
//     tau_b = 16th largest of the 256 thread maxima (disjoint-chunk bound,
//     exact-safe). pass 2: only threads whose own max >= tau re-read their
//     16 float4s (L2-hit) and append. still_prompt prompts skipped.
// k2: dual concurrent register tournaments (named barriers) + selection.
// k3: 512-block gather/convert of output sequence rows.

#define P_ 32
#define D_ 8
#define V_ 128000
#define S_ 2048
#define NBLK 64          // blocks per prompt in k1 (8 per beam)
#define CHUNK 16000      // elements per k1 block (V/8) = 4000 float4
#define N4 4000          // float4s per block
#define EOS_ID 2
#define MASK_INF 10000000.0f
#define PADV (-FLT_MAX)
#define CAP  32768       // candidate capacity per prompt (scaled list)
#define CAP0 8192        // candidate capacity per prompt (beam-0 raw list)
#define TILEH 2048       // candidates per half-tournament tile (16 slots * 128 thr)

// output layout (flat float32, tuple concat order)
#define OFF_ATTN 0
#define OFF_ASEQ 256
#define OFF_ALP  524544
#define OFF_FSEQ 524800
#define OFF_FLP  1049088

__device__ int   g_cnt[P_];              // zero-init at load; k2 resets
__device__ int   g_cnt0[P_];
__device__ float g_cv[P_ * CAP];
__device__ int   g_ci[P_ * CAP];
__device__ float g_c0v[P_ * CAP0];
__device__ int   g_c0i[P_ * CAP0];
__device__ int4  g_desc[2 * P_ * D_];    // {buf(0=alive,1=fin), src_beam, token, subpos(-1 none)}

#define FULLM 0xffffffffu
#define HBAR(id) asm volatile("bar.sync %0, %1;" :: "r"(id), "r"(128) : "memory")

__device__ __forceinline__ float max4(float4 v) {
    return fmaxf(fmaxf(v.x, v.y), fmaxf(v.z, v.w));
}

// ---------------- Kernel 1: thread-chunk self-threshold, MLP=4 rolled -------
__global__ void __launch_bounds__(256)
k1_scan(const float* __restrict__ probs, const float* __restrict__ alive_lp,
        const int* __restrict__ still_prompt, const int* __restrict__ is_first) {
    int blk = blockIdx.x;
    int p = blk >> 6;
    if (still_prompt[p]) return;              // passthrough prompt: no work
    int b = blk & 63;
    int d = b >> 3;
    int part = b & 7;
    int t = threadIdx.x, w = t >> 5, lane = t & 31;

    __shared__ float s_tm[256];
    __shared__ float s_tau;

    const float4* base = (const float4*)(probs + (long)(p * D_ + d) * V_ + part * CHUNK);
    const float4 pad4 = make_float4(PADV, PADV, PADV, PADV);

    // ---- pass 1: per-thread max, 4 batched loads per rolled iteration ------
    float tm = -FLT_MAX;
#pragma unroll 1
    for (int s = 0; s < 4; s++) {
        int j0 = (s * 4 + 0) * 256 + t;
        int j1 = (s * 4 + 1) * 256 + t;
        int j2 = (s * 4 + 2) * 256 + t;
        int j3 = (s * 4 + 3) * 256 + t;
        float4 a = base[j0];                  // j0..j2 always < 4000
        float4 bq = base[j1];
        float4 c = base[j2];
        float4 dq = (j3 < N4) ? base[j3] : pad4;
        tm = fmaxf(tm, fmaxf(fmaxf(max4(a), max4(bq)), fmaxf(max4(c), max4(dq))));
    }
    s_tm[t] = tm;
    __syncthreads();

    // ---- tau_b = 16th largest of 256 thread maxima (warp 0) ----------------
    if (w == 0) {
        float vv[8];
#pragma unroll
        for (int j = 0; j < 8; j++) vv[j] = s_tm[lane + 32 * j];
        float last = -FLT_MAX;
#pragma unroll
        for (int k = 0; k < 16; k++) {
            float bv = vv[0]; int bs = 0;
#pragma unroll
            for (int j = 1; j < 8; j++)
                if (vv[j] > bv) { bv = vv[j]; bs = j; }
            float cb = bv; int cl = lane;
#pragma unroll
            for (int off = 16; off; off >>= 1) {
                float ov = __shfl_xor_sync(FULLM, cb, off);
                int   ol = __shfl_xor_sync(FULLM, cl, off);
                if (ov > cb || (ov == cb && ol < cl)) { cb = ov; cl = ol; }
            }
            last = cb;
            if (lane == cl) vv[bs] = -FLT_MAX;
        }
        if (lane == 0) s_tau = last;
    }
    __syncthreads();

    float tauR = s_tau;                       // raw-space threshold (shared by both lists)

    // ---- pass 2: only threads whose own max >= tau re-read (L2-hit) --------
    if (tm >= tauR) {
        float scale = expf(alive_lp[p * D_ + d]);
        bool do0 = (d == 0) && (is_first[p] != 0);
        int fb0 = d * V_ + part * CHUNK;
#pragma unroll 1
        for (int i = 0; i < 16; i++) {
            int j = i * 256 + t;
            if (j >= N4) continue;
            float4 v = base[j];
            int fb = fb0 + j * 4;
            float vx[4] = {v.x, v.y, v.z, v.w};
#pragma unroll
            for (int cc = 0; cc < 4; cc++) {
                if (vx[cc] >= tauR) {
                    int pos = atomicAdd(&g_cnt[p], 1);
                    if (pos < CAP) { g_cv[p * CAP + pos] = vx[cc] * scale; g_ci[p * CAP + pos] = fb + cc; }
                    if (do0) {                // d==0: flat idx == token id
                        int pos0 = atomicAdd(&g_cnt0[p], 1);
                        if (pos0 < CAP0) { g_c0v[p * CAP0 + pos0] = vx[cc]; g_c0i[p * CAP0 + pos0] = fb + cc; }
                    }
                }
            }
        }
    }
}

// -------- half-block tournament: sorted top-16, 128 threads, named barrier ---
struct HalfScratch {
    float swv[4]; int swi[4]; int swt[4];
    int   s_win;
};

__device__ void half_top16(const float* __restrict__ gv, const int* __restrict__ gi,
                           int cnt, volatile float* bestv, volatile int* besti,
                           volatile HalfScratch* sc, int tb, int barid) {
    int t = threadIdx.x;
    int lt = t - tb;                          // 0..127
    int w2 = lt >> 5;                         // 0..3
    int lane = t & 31;
    float rv[17]; int ri[17];
    int ntile = (cnt + TILEH - 1) / TILEH;
    if (ntile < 1) ntile = 1;

    for (int tile = 0; tile < ntile; tile++) {
        int base = tile * TILEH;
#pragma unroll
        for (int k = 0; k < 16; k++) {
            int j = base + k * 128 + lt;
            bool ok = (j < cnt);
            rv[k] = ok ? gv[j] : -FLT_MAX;
            ri[k] = ok ? gi[j] : INT_MAX;
        }
        if (tile > 0 && lt < 16) { rv[16] = bestv[lt]; ri[16] = besti[lt]; }
        else                     { rv[16] = -FLT_MAX; ri[16] = INT_MAX; }

        for (int r = 0; r < 16; r++) {
            float bv = rv[0]; int bi = ri[0]; int bs = 0;
#pragma unroll
            for (int k = 1; k < 17; k++)
                if (rv[k] > bv || (rv[k] == bv && ri[k] < bi)) { bv = rv[k]; bi = ri[k]; bs = k; }
            int bt = lt;
#pragma unroll
            for (int off = 16; off; off >>= 1) {
                float ov = __shfl_xor_sync(FULLM, bv, off);
                int   oi = __shfl_xor_sync(FULLM, bi, off);
                int   ot = __shfl_xor_sync(FULLM, bt, off);
                if (ov > bv || (ov == bv && oi < bi)) { bv = ov; bi = oi; bt = ot; }
            }
            if (lane == 0) { sc->swv[w2] = bv; sc->swi[w2] = bi; sc->swt[w2] = bt; }
            HBAR(barid);
            if (lt == 0) {
                float fv = sc->swv[0]; int fi = sc->swi[0]; int ft = sc->swt[0];
#pragma unroll
                for (int q = 1; q < 4; q++)
                    if (sc->swv[q] > fv || (sc->swv[q] == fv && sc->swi[q] < fi)) {
                        fv = sc->swv[q]; fi = sc->swi[q]; ft = sc->swt[q];
                    }
                bestv[r] = fv; besti[r] = fi; sc->s_win = ft;
            }
            HBAR(barid);
            if (lt == sc->s_win) { rv[bs] = -FLT_MAX; ri[bs] = INT_MAX; }
        }
        HBAR(barid);
    }
}

// ---------------- Kernel 2: dual tournament + beam-search selection ----------
__global__ void __launch_bounds__(256)
k2_select(const float* __restrict__ alive_lp, const float* __restrict__ fin_lp,
          const int* __restrict__ still_prompt,
          const int* __restrict__ is_first,
          const int* __restrict__ cur_pos_p, float* __restrict__ out) {
    int p = blockIdx.x;
    int t = threadIdx.x;

    __shared__ float fv[16];  __shared__ int fi[16];
    __shared__ float fv0[16]; __shared__ int fi0[16];
    __shared__ HalfScratch scA, scB;

    bool sp = still_prompt[p] != 0;
    bool first = is_first[p] != 0;
    int cnt  = min(g_cnt[p], CAP);
    int cnt0 = min(g_cnt0[p], CAP0);

    if (!sp) {
        if (t < 128)
            half_top16(g_cv + p * CAP, g_ci + p * CAP, cnt, fv, fi,
                       (volatile HalfScratch*)&scA, 0, 1);
        else if (first)
            half_top16(g_c0v + p * CAP0, g_c0i + p * CAP0, cnt0, fv0, fi0,
                       (volatile HalfScratch*)&scB, 128, 2);
    }
    __syncthreads();

    if (t == 0) {
        g_cnt[p] = 0; g_cnt0[p] = 0;          // reset for next graph replay
        int cp = *cur_pos_p;

        float lp16[16]; int tok16[16], beam16[16]; bool fin16[16];
        if (!sp) {
            for (int k = 0; k < 16; k++) {
                int idx = fi[k];
                int bm = idx / V_;
                beam16[k] = bm;
                tok16[k]  = idx - bm * V_;
                lp16[k]   = logf(fv[k]);      // log(p*e^a) == a + log p
            }
            if (first) {
                float al0 = alive_lp[p * D_];
                for (int k = 0; k < 16; k++) {
                    tok16[k] = fi0[k];        // flat idx within beam 0 == token
                    lp16[k]  = al0 + logf(fv0[k]);
                }
            }
            for (int k = 0; k < 16; k++) fin16[k] = (tok16[k] == EOS_ID);
        }

        int na[8]; float nav[8];
        int nf[8]; float nfv[8];
        if (!sp) {
            float am[16]; bool used[16];
            for (int k = 0; k < 16; k++) { am[k] = lp16[k] + (fin16[k] ? -MASK_INF : 0.0f); used[k] = false; }
            for (int j = 0; j < 8; j++) {
                int bi = -1; float bv = 0.0f;
                for (int k = 0; k < 16; k++)
                    if (!used[k] && (bi < 0 || am[k] > bv)) { bi = k; bv = am[k]; }
                used[bi] = true; na[j] = bi; nav[j] = bv;
            }
            float cl[24]; bool used2[24];
            for (int j = 0; j < 8; j++) cl[j] = fin_lp[p * D_ + j];
            for (int k = 0; k < 16; k++) cl[8 + k] = lp16[k] + (fin16[k] ? 0.0f : -MASK_INF);
            for (int k = 0; k < 24; k++) used2[k] = false;
            for (int j = 0; j < 8; j++) {
                int bi = -1; float bv = 0.0f;
                for (int k = 0; k < 24; k++)
                    if (!used2[k] && (bi < 0 || cl[k] > bv)) { bi = k; bv = cl[k]; }
                used2[bi] = true; nf[j] = bi; nfv[j] = bv;
            }
        }

        for (int j = 0; j < 8; j++) {
            out[OFF_ATTN + p * D_ + j] = sp ? (float)j : (float)beam16[na[j]];
            out[OFF_ALP  + p * D_ + j] = sp ? alive_lp[p * D_ + j] : nav[j];
            out[OFF_FLP  + p * D_ + j] = sp ? fin_lp[p * D_ + j]   : nfv[j];

            int4 da, df;
            if (sp) {
                da = make_int4(0, j, 0, -1);
                df = make_int4(1, j, 0, -1);
            } else {
                da = make_int4(0, beam16[na[j]], tok16[na[j]], cp);
                if (nf[j] < 8) df = make_int4(1, nf[j], 0, -1);
                else { int k = nf[j] - 8; df = make_int4(0, beam16[k], tok16[k], cp); }
            }
            g_desc[p * D_ + j] = da;
            g_desc[P_ * D_ + p * D_ + j] = df;
        }
    }
}

// ---------------- Kernel 3: gather output sequences --------------------------
__global__ void __launch_bounds__(256)
k3_gather(const int* __restrict__ alive_seq, const int* __restrict__ fin_seq,
          float* __restrict__ out) {
    int r = blockIdx.x;                       // 0..511
    int4 dsc = g_desc[r];
    bool isAlive = r < P_ * D_;
    int rr = isAlive ? r : r - P_ * D_;
    int p = rr >> 3;
    const int* srcbase = (dsc.x ? fin_seq : alive_seq) + (long)(p * D_ + dsc.y) * S_;
    long dst = (isAlive ? (long)OFF_ASEQ : (long)OFF_FSEQ) + (long)rr * S_;
    const int4* s4 = (const int4*)srcbase;
    float4* o4 = (float4*)(out + dst);
    int subpos = dsc.w, tok = dsc.z;
    for (int j = threadIdx.x; j < S_ / 4; j += 256) {
        int4 v = s4[j];
        int base = j * 4;
        if (subpos >= base && subpos < base + 4) {
            int* vp = (int*)&v;
            vp[subpos - base] = tok;
        }
        o4[j] = make_float4((float)v.x, (float)v.y, (float)v.z, (float)v.w);
    }
}

extern "C" void kernel_launch(void* const* d_in, const int* in_sizes, int n_in,
                              void* d_out, int out_size) {
    const float* probs        = (const float*)d_in[0];
    const int*   alive_seq    = (const int*)d_in[1];
    const int*   fin_seq      = (const int*)d_in[2];
    const float* alive_lp     = (const float*)d_in[3];
    const float* fin_lp       = (const float*)d_in[4];
    const int*   still_prompt = (const int*)d_in[5];
    const int*   is_first     = (const int*)d_in[6];
    const int*   cur_pos      = (const int*)d_in[7];
    float* out = (float*)d_out;

    k1_scan<<<P_ * NBLK, 256>>>(probs, alive_lp, still_prompt, is_first);
    k2_select<<<P_, 256>>>(alive_lp, fin_lp, still_prompt, is_first, cur_pos, out);
    k3_gather<<<2 * P_ * D_, 256>>>(alive_seq, fin_seq, out);
}